// round 15
// baseline (speedup 1.0000x reference)
#include <cuda_runtime.h>
#include <cuda_fp16.h>
#include <cstdint>
#include <math.h>

#define TOKENS 4096
#define HS 1024
#define FFN 4096
#define NE 8
#define CAP 512

// ---------------- scratch (static device globals; no allocations) -----------
__device__ int    g_expert[TOKENS * 2];
__device__ float  g_weight[TOKENS * 2];
__device__ int    g_rows[NE * 1024];
__device__ int    g_pos[2 * TOKENS];
__device__ __half g_xh[(size_t)TOKENS * HS];       // x fp16 (written by router)
__device__ __half g_w1h[(size_t)NE * HS * FFN];    // w1 fp16
__device__ __half g_w2h[(size_t)NE * FFN * HS];    // w2 fp16
__device__ __half g_h[(size_t)NE * 1024 * FFN];    // gemm1 out fp16
__device__ __half g_yeh[(size_t)NE * 1024 * HS];   // gemm2 out fp16

// ---------------- GEMM config -------------------------------------------------
#define BN 128
#define NTH 256
#define NSTG 3
#define SLABW 68
#define SLABB (16 * SLABW * 4)

// ---------------- helpers -----------------------------------------------------
__device__ __forceinline__ uint32_t smem_u32(const void* p) {
    uint32_t a;
    asm("{ .reg .u64 t; cvta.to.shared.u64 t, %1; cvt.u32.u64 %0, t; }" : "=r"(a) : "l"(p));
    return a;
}
__device__ __forceinline__ uint32_t pack2(float lo, float hi) {
    __half2 h = __floats2half2_rn(lo, hi);
    return *reinterpret_cast<uint32_t*>(&h);
}
__device__ __forceinline__ void cp16(uint32_t sdst, const void* gsrc) {
    asm volatile("cp.async.cg.shared.global [%0], [%1], 16;" :: "r"(sdst), "l"(gsrc));
}
__device__ __forceinline__ void cp16z(uint32_t sdst, const void* gsrc, int nbytes) {
    asm volatile("cp.async.cg.shared.global [%0], [%1], 16, %2;"
                 :: "r"(sdst), "l"(gsrc), "r"(nbytes));
}
__device__ __forceinline__ void cp_commit() { asm volatile("cp.async.commit_group;"); }
template <int N> __device__ __forceinline__ void cp_wait() {
    asm volatile("cp.async.wait_group %0;" :: "n"(N));
}
__device__ __forceinline__ void ldsm4(uint32_t r[4], uint32_t addr) {
    asm volatile("ldmatrix.sync.aligned.m8n8.x4.shared.b16 {%0,%1,%2,%3}, [%4];"
                 : "=r"(r[0]), "=r"(r[1]), "=r"(r[2]), "=r"(r[3]) : "r"(addr));
}
__device__ __forceinline__ void ldsm4t(uint32_t r[4], uint32_t addr) {
    asm volatile("ldmatrix.sync.aligned.m8n8.x4.trans.shared.b16 {%0,%1,%2,%3}, [%4];"
                 : "=r"(r[0]), "=r"(r[1]), "=r"(r[2]), "=r"(r[3]) : "r"(addr));
}
__device__ __forceinline__ void mma16816(float c[4], const uint32_t a[4],
                                         uint32_t b0, uint32_t b1) {
    asm volatile(
        "mma.sync.aligned.m16n8k16.row.col.f32.f16.f16.f32 "
        "{%0,%1,%2,%3}, {%4,%5,%6,%7}, {%8,%9}, {%0,%1,%2,%3};"
        : "+f"(c[0]), "+f"(c[1]), "+f"(c[2]), "+f"(c[3])
        : "r"(a[0]), "r"(a[1]), "r"(a[2]), "r"(a[3]), "r"(b0), "r"(b1));
}
__device__ __forceinline__ float gelu_tanh(float v) {
    float v3 = v * v * v;
    return 0.5f * v * (1.0f + tanhf(0.7978845608028654f * (v + 0.044715f * v3)));
}

// ---------------- router + x->fp16 (fused) ---------------------------------------
__global__ void router_kernel(const float* __restrict__ x, const float* __restrict__ rw) {
    int warp = threadIdx.x >> 5, lane = threadIdx.x & 31;
    int t = blockIdx.x * 8 + warp;
    const float* xr = x + (size_t)t * HS;
    __half* xhr = g_xh + (size_t)t * HS;
    float acc[NE];
#pragma unroll
    for (int e = 0; e < NE; e++) acc[e] = 0.f;
    for (int j = lane; j < HS; j += 32) {
        float xv = xr[j];
        xhr[j] = __float2half_rn(xv);          // fused x -> fp16
        const float4* r4 = reinterpret_cast<const float4*>(rw + (size_t)j * NE);
        float4 ra = r4[0], rb = r4[1];
        acc[0] += xv * ra.x; acc[1] += xv * ra.y; acc[2] += xv * ra.z; acc[3] += xv * ra.w;
        acc[4] += xv * rb.x; acc[5] += xv * rb.y; acc[6] += xv * rb.z; acc[7] += xv * rb.w;
    }
#pragma unroll
    for (int o = 16; o > 0; o >>= 1)
#pragma unroll
        for (int e = 0; e < NE; e++) acc[e] += __shfl_xor_sync(0xffffffffu, acc[e], o);
    if (lane == 0) {
        float m = acc[0];
#pragma unroll
        for (int e = 1; e < NE; e++) m = fmaxf(m, acc[e]);
        float s[NE]; float sum = 0.f;
#pragma unroll
        for (int e = 0; e < NE; e++) { s[e] = expf(acc[e] - m); sum += s[e]; }
        float inv = 1.f / sum;
        int e0 = 0; float m0 = s[0];
#pragma unroll
        for (int e = 1; e < NE; e++) if (s[e] > m0) { m0 = s[e]; e0 = e; }
        int e1 = -1; float m1 = -1.f;
#pragma unroll
        for (int e = 0; e < NE; e++) if (e != e0 && s[e] > m1) { m1 = s[e]; e1 = e; }
        g_expert[t * 2 + 0] = e0; g_expert[t * 2 + 1] = e1;
        g_weight[t * 2 + 0] = m0 * inv; g_weight[t * 2 + 1] = m1 * inv;
    }
}

// ---------------- dispatch: two-phase (count half0 || rank halves) --------------
__global__ void dispatch_kernel() {
    __shared__ int se[TOKENS * 2];   // 32KB
    __shared__ int chalf[16];
    for (int i = threadIdx.x; i < TOKENS * 2 / 4; i += 1024)
        reinterpret_cast<int4*>(se)[i] = reinterpret_cast<const int4*>(g_expert)[i];
    __syncthreads();

    int w = threadIdx.x >> 5, lane = threadIdx.x & 31;
    int pair = w >> 1, h = w & 1;
    int k = pair >> 3, e = pair & 7;

    if (h == 0) {
        int c = 0;
        for (int t = lane; t < TOKENS / 2; t += 32)
            c += (se[t * 2 + k] == e);
#pragma unroll
        for (int o = 16; o > 0; o >>= 1) c += __shfl_xor_sync(0xffffffffu, c, o);
        if (lane == 0) chalf[pair] = c;
    }
    __syncthreads();

    int count = h ? chalf[pair] : 0;
    const int base0 = h * (TOKENS / 2);
    for (int base = base0; base < base0 + TOKENS / 2; base += 32) {
        int t = base + lane;
        bool match = (se[t * 2 + k] == e);
        unsigned mask = __ballot_sync(0xffffffffu, match);
        int r = count + __popc(mask & ((1u << lane) - 1u));
        if (match) {
            if (r < CAP) {
                int slot = k * CAP + r;
                g_rows[e * 1024 + slot] = t;
                g_pos[k * TOKENS + t] = e * 1024 + slot;
            } else {
                g_pos[k * TOKENS + t] = -1;
            }
        }
        count += __popc(mask);
    }
    if (h == 1)
        for (int s = count + lane; s < CAP; s += 32)
            g_rows[e * 1024 + k * CAP + s] = -1;
}

// ---------------- f32 -> fp16 weight converts ------------------------------------
__global__ void convert_w(const float* __restrict__ src, __half* __restrict__ dst) {
    int i = blockIdx.x * blockDim.x + threadIdx.x;
    float4 v = reinterpret_cast<const float4*>(src)[i];
    reinterpret_cast<uint2*>(dst)[i] = make_uint2(pack2(v.x, v.y), pack2(v.z, v.w));
}
__global__ void convert_w_strided(const float* __restrict__ src, __half* __restrict__ dst,
                                  int n4) {
    int stride = gridDim.x * blockDim.x;
    for (int i = blockIdx.x * blockDim.x + threadIdx.x; i < n4; i += stride) {
        float4 v = reinterpret_cast<const float4*>(src)[i];
        reinterpret_cast<uint2*>(dst)[i] = make_uint2(pack2(v.x, v.y), pack2(v.z, v.w));
    }
}

// ---------------- fp16 cp.async GEMM: BM=128, 2 CTAs/SM --------------------------
// FIRST: A gathered from g_xh via g_rows (zero-fill empty slots); else linear g_h.
template <bool FIRST, int BMT, int MF>
__global__ void __launch_bounds__(NTH, 2)
moe_gemm(const __half* __restrict__ A0, const __half* __restrict__ W0) {
    constexpr int K = FIRST ? HS : FFN;
    constexpr int N = FIRST ? FFN : HS;
    constexpr int KT2 = K / 64;
    constexpr int A_SUB = BMT * 64;
    constexpr int B_SUB = 8192;
    constexpr int STAGE = 2 * A_SUB + 2 * B_SUB;
    constexpr int SM_BOFF = 2 * A_SUB;
    extern __shared__ char smem[];
    const uint32_t sbase = smem_u32(smem);
    const int tid = threadIdx.x, wid = tid >> 5, lane = tid & 31;
    const int e = blockIdx.z, by = blockIdx.y, nb = blockIdx.x;
    const int wm = wid & 3, wn = wid >> 2;
    const int grp = lane >> 2, qid = lane & 3;

    const __half* Wbase = W0 + (size_t)e * K * N + nb * BN;

    const __half* aPtr[MF];
    int aSz[MF];
    {
        const int r = tid >> 2, kc = (tid & 3) * 8;
#pragma unroll
        for (int p = 0; p < MF; p++) {
            if (FIRST) {
                int tok = g_rows[e * 1024 + by * BMT + p * 64 + r];
                aSz[p] = (tok >= 0) ? 16 : 0;
                aPtr[p] = A0 + (size_t)(tok >= 0 ? tok : 0) * K + kc;
            } else {
                aSz[p] = 16;
                aPtr[p] = A0 + (size_t)(e * 1024 + by * BMT + p * 64 + r) * K + kc;
            }
        }
    }
    const uint32_t aDst = sbase + (tid >> 2) * 64 + ((((tid & 3)) ^ (((tid >> 2) >> 1) & 3)) << 4);
    const __half* bSrc = Wbase + (size_t)(tid >> 4) * N + (tid & 15) * 8;
    const uint32_t bDst = sbase + SM_BOFF + (tid >> 4) * 256 + (((tid & 15) ^ ((tid >> 4) & 7)) << 4);

    auto issue = [&](int kt2) {
        const uint32_t st = (uint32_t)(kt2 % NSTG) * STAGE;
#pragma unroll
        for (int h = 0; h < 2; h++) {
#pragma unroll
            for (int p = 0; p < MF; p++)
                cp16z(aDst + st + h * A_SUB + p * 4096,
                      aPtr[p] + kt2 * 64 + h * 32, aSz[p]);
            const __half* bp = bSrc + (size_t)(kt2 * 64 + h * 32) * N;
#pragma unroll
            for (int p = 0; p < 2; p++)
                cp16(bDst + st + h * B_SUB + p * 4096, bp + (size_t)p * 16 * N);
        }
    };

    uint32_t aA, bA;
    {
        int r0 = wm * (16 * MF) + (lane & 15);
        int c0 = lane >> 4;
        aA = sbase + r0 * 64 + ((c0 ^ ((r0 >> 1) & 3)) << 4);
        int k0 = lane & 15;
        int cb0 = wn * 8 + (lane >> 4);
        bA = sbase + SM_BOFF + k0 * 256 + ((cb0 ^ (k0 & 7)) << 4);
    }

    float c[MF][8][4];
#pragma unroll
    for (int mf = 0; mf < MF; mf++)
#pragma unroll
        for (int nn = 0; nn < 8; nn++)
#pragma unroll
            for (int i = 0; i < 4; i++) c[mf][nn][i] = 0.f;

    issue(0); cp_commit();
    issue(1); cp_commit();

#pragma unroll 1
    for (int kt2 = 0; kt2 < KT2; kt2++) {
        cp_wait<1>();
        __syncthreads();
        if (kt2 + 2 < KT2) issue(kt2 + 2);
        cp_commit();

        const uint32_t st = (uint32_t)(kt2 % NSTG) * STAGE;
#pragma unroll
        for (int h = 0; h < 2; h++) {
            const uint32_t sA = aA + st + h * A_SUB;
            const uint32_t sB = bA + st + h * B_SUB;
#pragma unroll
            for (int kh = 0; kh < 2; kh++) {
                uint32_t a[MF][4], b[4][4];
#pragma unroll
                for (int mf = 0; mf < MF; mf++)
                    ldsm4(a[mf], (sA + mf * 1024) ^ (kh << 5));
#pragma unroll
                for (int nf = 0; nf < 4; nf++)
                    ldsm4t(b[nf], (sB + kh * 4096) ^ (nf << 5));
#pragma unroll
                for (int mf = 0; mf < MF; mf++)
#pragma unroll
                    for (int nf = 0; nf < 4; nf++) {
                        mma16816(c[mf][nf * 2 + 0], a[mf], b[nf][0], b[nf][1]);
                        mma16816(c[mf][nf * 2 + 1], a[mf], b[nf][2], b[nf][3]);
                    }
            }
        }
    }
    __syncthreads();

    // ---- epilogue: fp16 output for BOTH gemms (g_h / g_yeh) ----
    float* slab = reinterpret_cast<float*>(smem + wid * SLABB);
    const int er = lane >> 1, ec = (lane & 1) * 32;
#pragma unroll
    for (int mf = 0; mf < MF; mf++) {
#pragma unroll
        for (int nn = 0; nn < 8; nn++)
#pragma unroll
            for (int i = 0; i < 4; i++) {
                float v = c[mf][nn][i];
                if (FIRST) v = gelu_tanh(v);
                slab[(grp + (i >> 1) * 8) * SLABW + nn * 8 + qid * 2 + (i & 1)] = v;
            }
        __syncwarp();
        size_t row = (size_t)e * 1024 + by * BMT + wm * (16 * MF) + mf * 16 + er;
        int col = nb * BN + wn * 64 + ec;
        float v[32];
#pragma unroll
        for (int j = 0; j < 8; j++) {
            float4 t4 = *reinterpret_cast<const float4*>(slab + er * SLABW + ec + 4 * j);
            v[4 * j] = t4.x; v[4 * j + 1] = t4.y; v[4 * j + 2] = t4.z; v[4 * j + 3] = t4.w;
        }
        uint4* dst = reinterpret_cast<uint4*>((FIRST ? g_h : g_yeh) + row * N + col);
#pragma unroll
        for (int j = 0; j < 4; j++)
            dst[j] = make_uint4(pack2(v[8 * j], v[8 * j + 1]), pack2(v[8 * j + 2], v[8 * j + 3]),
                                pack2(v[8 * j + 4], v[8 * j + 5]), pack2(v[8 * j + 6], v[8 * j + 7]));
        __syncwarp();
    }
}

// ---------------- combine (fp16 y) -----------------------------------------------
__global__ void combine_kernel(const float* __restrict__ bias, float* __restrict__ out) {
    int t = blockIdx.x;
    int j = threadIdx.x;
    float4 acc = reinterpret_cast<const float4*>(bias)[j];
    int p0 = g_pos[t];
    int p1 = g_pos[TOKENS + t];
    float w0 = g_weight[t * 2 + 0], w1 = g_weight[t * 2 + 1];
    if (p0 >= 0) {
        uint2 hv = *reinterpret_cast<const uint2*>(g_yeh + (size_t)p0 * HS + 4 * j);
        float2 f0 = __half22float2(*reinterpret_cast<__half2*>(&hv.x));
        float2 f1 = __half22float2(*reinterpret_cast<__half2*>(&hv.y));
        acc.x += w0 * f0.x; acc.y += w0 * f0.y; acc.z += w0 * f1.x; acc.w += w0 * f1.y;
    }
    if (p1 >= 0) {
        uint2 hv = *reinterpret_cast<const uint2*>(g_yeh + (size_t)p1 * HS + 4 * j);
        float2 f0 = __half22float2(*reinterpret_cast<__half2*>(&hv.x));
        float2 f1 = __half22float2(*reinterpret_cast<__half2*>(&hv.y));
        acc.x += w1 * f0.x; acc.y += w1 * f0.y; acc.z += w1 * f1.x; acc.w += w1 * f1.y;
    }
    reinterpret_cast<float4*>(out + (size_t)t * HS)[j] = acc;
}

// ---------------- launch -----------------------------------------------------------
#define SMEMG (NSTG * (2 * 128 * 64 + 2 * 8192))   // 98304 (both GEMMs, BM=128)

extern "C" void kernel_launch(void* const* d_in, const int* in_sizes, int n_in,
                              void* d_out, int out_size) {
    const float* x    = (const float*)d_in[0];
    const float* rw   = (const float*)d_in[1];
    const float* w1   = (const float*)d_in[2];
    const float* w2   = (const float*)d_in[3];
    const float* bias = (const float*)d_in[4];
    float* out = (float*)d_out;

    static cudaStream_t s2 = nullptr, s3 = nullptr;
    static cudaEvent_t evA = nullptr, evG = nullptr, evW2 = nullptr;
    if (s2 == nullptr) {
        int loPri = 0, hiPri = 0;
        cudaDeviceGetStreamPriorityRange(&loPri, &hiPri);
        cudaStreamCreateWithFlags(&s2, cudaStreamNonBlocking);
        cudaStreamCreateWithPriority(&s3, cudaStreamNonBlocking, loPri);
        cudaEventCreateWithFlags(&evA, cudaEventDisableTiming);
        cudaEventCreateWithFlags(&evG, cudaEventDisableTiming);
        cudaEventCreateWithFlags(&evW2, cudaEventDisableTiming);
    }

    cudaFuncSetAttribute((const void*)moe_gemm<true, 128, 2>,
                         cudaFuncAttributeMaxDynamicSharedMemorySize, SMEMG);
    cudaFuncSetAttribute((const void*)moe_gemm<false, 128, 2>,
                         cudaFuncAttributeMaxDynamicSharedMemorySize, SMEMG);

    __half* w1h; cudaGetSymbolAddress((void**)&w1h, g_w1h);
    __half* w2h; cudaGetSymbolAddress((void**)&w2h, g_w2h);
    __half* xh;  cudaGetSymbolAddress((void**)&xh,  g_xh);
    __half* hh;  cudaGetSymbolAddress((void**)&hh,  g_h);

    const int WN4 = NE * HS * FFN / 4;

    // fork: routing (router[+x->fp16] + dispatch) on s2;
    //       convert_w2 (low-priority, small grid) on s3; convert_w1 on main.
    cudaEventRecord(evA, 0);
    cudaStreamWaitEvent(s2, evA, 0);
    cudaStreamWaitEvent(s3, evA, 0);

    router_kernel<<<TOKENS / 8, 256, 0, s2>>>(x, rw);   // also writes g_xh
    dispatch_kernel<<<1, 1024, 0, s2>>>();
    cudaEventRecord(evG, s2);                           // g_rows + g_xh ready

    convert_w_strided<<<1184, 256, 0, s3>>>(w2, w2h, WN4);  // drains under gemm1
    cudaEventRecord(evW2, s3);                              // w2h ready

    convert_w<<<WN4 / 256, 256>>>(w1, w1h);                 // main
    cudaStreamWaitEvent(0, evG, 0);

    moe_gemm<true, 128, 2><<<dim3(FFN / BN, 1024 / 128, NE), NTH, SMEMG>>>(xh, w1h);
    cudaStreamWaitEvent(0, evW2, 0);
    moe_gemm<false, 128, 2><<<dim3(HS / BN, 1024 / 128, NE), NTH, SMEMG>>>(hh, w2h);
    combine_kernel<<<TOKENS, 256>>>(bias, out);
}

// round 16
// speedup vs baseline: 1.0485x; 1.0485x over previous
#include <cuda_runtime.h>
#include <cuda_fp16.h>
#include <cstdint>
#include <math.h>

#define TOKENS 4096
#define HS 1024
#define FFN 4096
#define NE 8
#define CAP 512

// ---------------- scratch (static device globals; no allocations) -----------
__device__ int    g_expert[TOKENS * 2];
__device__ float  g_weight[TOKENS * 2];
__device__ int    g_rows[NE * 1024];
__device__ int    g_pos[2 * TOKENS];
__device__ __half g_xh[(size_t)TOKENS * HS];       // x fp16
__device__ __half g_w1h[(size_t)NE * HS * FFN];    // w1 fp16
__device__ __half g_w2h[(size_t)NE * FFN * HS];    // w2 fp16
__device__ __half g_h[(size_t)NE * 1024 * FFN];    // gemm1 out fp16
__device__ __half g_yeh[(size_t)NE * 1024 * HS];   // gemm2 out fp16

// ---------------- GEMM config -------------------------------------------------
#define BN 128
#define NTH 128                  // 4 warps, 64x64 per warp
#define NSTG 3
#define SLABW 68
#define SLABB (16 * SLABW * 4)

// ---------------- helpers -----------------------------------------------------
__device__ __forceinline__ uint32_t smem_u32(const void* p) {
    uint32_t a;
    asm("{ .reg .u64 t; cvta.to.shared.u64 t, %1; cvt.u32.u64 %0, t; }" : "=r"(a) : "l"(p));
    return a;
}
__device__ __forceinline__ uint32_t pack2(float lo, float hi) {
    __half2 h = __floats2half2_rn(lo, hi);
    return *reinterpret_cast<uint32_t*>(&h);
}
__device__ __forceinline__ void cp16(uint32_t sdst, const void* gsrc) {
    asm volatile("cp.async.cg.shared.global [%0], [%1], 16;" :: "r"(sdst), "l"(gsrc));
}
__device__ __forceinline__ void cp16z(uint32_t sdst, const void* gsrc, int nbytes) {
    asm volatile("cp.async.cg.shared.global [%0], [%1], 16, %2;"
                 :: "r"(sdst), "l"(gsrc), "r"(nbytes));
}
__device__ __forceinline__ void cp_commit() { asm volatile("cp.async.commit_group;"); }
template <int N> __device__ __forceinline__ void cp_wait() {
    asm volatile("cp.async.wait_group %0;" :: "n"(N));
}
__device__ __forceinline__ void ldsm4(uint32_t r[4], uint32_t addr) {
    asm volatile("ldmatrix.sync.aligned.m8n8.x4.shared.b16 {%0,%1,%2,%3}, [%4];"
                 : "=r"(r[0]), "=r"(r[1]), "=r"(r[2]), "=r"(r[3]) : "r"(addr));
}
__device__ __forceinline__ void ldsm4t(uint32_t r[4], uint32_t addr) {
    asm volatile("ldmatrix.sync.aligned.m8n8.x4.trans.shared.b16 {%0,%1,%2,%3}, [%4];"
                 : "=r"(r[0]), "=r"(r[1]), "=r"(r[2]), "=r"(r[3]) : "r"(addr));
}
__device__ __forceinline__ void mma16816(float c[4], const uint32_t a[4],
                                         uint32_t b0, uint32_t b1) {
    asm volatile(
        "mma.sync.aligned.m16n8k16.row.col.f32.f16.f16.f32 "
        "{%0,%1,%2,%3}, {%4,%5,%6,%7}, {%8,%9}, {%0,%1,%2,%3};"
        : "+f"(c[0]), "+f"(c[1]), "+f"(c[2]), "+f"(c[3])
        : "r"(a[0]), "r"(a[1]), "r"(a[2]), "r"(a[3]), "r"(b0), "r"(b1));
}
__device__ __forceinline__ float gelu_tanh(float v) {
    float v3 = v * v * v;
    return 0.5f * v * (1.0f + tanhf(0.7978845608028654f * (v + 0.044715f * v3)));
}

// ---------------- router (R14 version, no fusion) -------------------------------
__global__ void router_kernel(const float* __restrict__ x, const float* __restrict__ rw) {
    int warp = threadIdx.x >> 5, lane = threadIdx.x & 31;
    int t = blockIdx.x * 8 + warp;
    const float* xr = x + (size_t)t * HS;
    float acc[NE];
#pragma unroll
    for (int e = 0; e < NE; e++) acc[e] = 0.f;
    for (int j = lane; j < HS; j += 32) {
        float xv = xr[j];
        const float4* r4 = reinterpret_cast<const float4*>(rw + (size_t)j * NE);
        float4 ra = r4[0], rb = r4[1];
        acc[0] += xv * ra.x; acc[1] += xv * ra.y; acc[2] += xv * ra.z; acc[3] += xv * ra.w;
        acc[4] += xv * rb.x; acc[5] += xv * rb.y; acc[6] += xv * rb.z; acc[7] += xv * rb.w;
    }
#pragma unroll
    for (int o = 16; o > 0; o >>= 1)
#pragma unroll
        for (int e = 0; e < NE; e++) acc[e] += __shfl_xor_sync(0xffffffffu, acc[e], o);
    if (lane == 0) {
        float m = acc[0];
#pragma unroll
        for (int e = 1; e < NE; e++) m = fmaxf(m, acc[e]);
        float s[NE]; float sum = 0.f;
#pragma unroll
        for (int e = 0; e < NE; e++) { s[e] = expf(acc[e] - m); sum += s[e]; }
        float inv = 1.f / sum;
        int e0 = 0; float m0 = s[0];
#pragma unroll
        for (int e = 1; e < NE; e++) if (s[e] > m0) { m0 = s[e]; e0 = e; }
        int e1 = -1; float m1 = -1.f;
#pragma unroll
        for (int e = 0; e < NE; e++) if (e != e0 && s[e] > m1) { m1 = s[e]; e1 = e; }
        g_expert[t * 2 + 0] = e0; g_expert[t * 2 + 1] = e1;
        g_weight[t * 2 + 0] = m0 * inv; g_weight[t * 2 + 1] = m1 * inv;
    }
}

// ---------------- dispatch: two-phase (validated) --------------------------------
__global__ void dispatch_kernel() {
    __shared__ int se[TOKENS * 2];
    __shared__ int chalf[16];
    for (int i = threadIdx.x; i < TOKENS * 2 / 4; i += 1024)
        reinterpret_cast<int4*>(se)[i] = reinterpret_cast<const int4*>(g_expert)[i];
    __syncthreads();

    int w = threadIdx.x >> 5, lane = threadIdx.x & 31;
    int pair = w >> 1, h = w & 1;
    int k = pair >> 3, e = pair & 7;

    if (h == 0) {
        int c = 0;
        for (int t = lane; t < TOKENS / 2; t += 32)
            c += (se[t * 2 + k] == e);
#pragma unroll
        for (int o = 16; o > 0; o >>= 1) c += __shfl_xor_sync(0xffffffffu, c, o);
        if (lane == 0) chalf[pair] = c;
    }
    __syncthreads();

    int count = h ? chalf[pair] : 0;
    const int base0 = h * (TOKENS / 2);
    for (int base = base0; base < base0 + TOKENS / 2; base += 32) {
        int t = base + lane;
        bool match = (se[t * 2 + k] == e);
        unsigned mask = __ballot_sync(0xffffffffu, match);
        int r = count + __popc(mask & ((1u << lane) - 1u));
        if (match) {
            if (r < CAP) {
                int slot = k * CAP + r;
                g_rows[e * 1024 + slot] = t;
                g_pos[k * TOKENS + t] = e * 1024 + slot;
            } else {
                g_pos[k * TOKENS + t] = -1;
            }
        }
        count += __popc(mask);
    }
    if (h == 1)
        for (int s = count + lane; s < CAP; s += 32)
            g_rows[e * 1024 + k * CAP + s] = -1;
}

// ---------------- f32 -> fp16 converts -------------------------------------------
__global__ void convert_w(const float* __restrict__ src, __half* __restrict__ dst) {
    int i = blockIdx.x * blockDim.x + threadIdx.x;
    float4 v = reinterpret_cast<const float4*>(src)[i];
    reinterpret_cast<uint2*>(dst)[i] = make_uint2(pack2(v.x, v.y), pack2(v.z, v.w));
}
__global__ void convert_w_strided(const float* __restrict__ src, __half* __restrict__ dst,
                                  int n4) {
    int stride = gridDim.x * blockDim.x;
    for (int i = blockIdx.x * blockDim.x + threadIdx.x; i < n4; i += stride) {
        float4 v = reinterpret_cast<const float4*>(src)[i];
        reinterpret_cast<uint2*>(dst)[i] = make_uint2(pack2(v.x, v.y), pack2(v.z, v.w));
    }
}

// ---------------- fp16 cp.async GEMM: 128 thr, 4 warps x (64x64), 2 CTAs/SM ------
// FIRST: A gathered from g_xh via g_rows (zero-fill); else linear g_h.
template <bool FIRST>
__global__ void __launch_bounds__(NTH, 2)
moe_gemm(const __half* __restrict__ A0, const __half* __restrict__ W0) {
    constexpr int K = FIRST ? HS : FFN;
    constexpr int N = FIRST ? FFN : HS;
    constexpr int KT2 = K / 64;
    constexpr int BMT = 128;
    constexpr int A_SUB = BMT * 64;            // 8192
    constexpr int B_SUB = 8192;
    constexpr int STAGE = 2 * A_SUB + 2 * B_SUB;
    constexpr int SM_BOFF = 2 * A_SUB;
    extern __shared__ char smem[];
    const uint32_t sbase = smem_u32(smem);
    const int tid = threadIdx.x, wid = tid >> 5, lane = tid & 31;
    const int e = blockIdx.z, by = blockIdx.y, nb = blockIdx.x;
    const int wm = wid & 1, wn = wid >> 1;     // 2x2 warps, 64x64 per warp
    const int grp = lane >> 2, qid = lane & 3;

    const __half* Wbase = W0 + (size_t)e * K * N + nb * BN;

    // A: 4 row-groups of 32 per thread (r = tid>>2 in 0..31)
    const __half* aPtr[4];
    int aSz[4];
    {
        const int r = tid >> 2, kc = (tid & 3) * 8;
#pragma unroll
        for (int p = 0; p < 4; p++) {
            if (FIRST) {
                int tok = g_rows[e * 1024 + by * BMT + p * 32 + r];
                aSz[p] = (tok >= 0) ? 16 : 0;
                aPtr[p] = A0 + (size_t)(tok >= 0 ? tok : 0) * K + kc;
            } else {
                aSz[p] = 16;
                aPtr[p] = A0 + (size_t)(e * 1024 + by * BMT + p * 32 + r) * K + kc;
            }
        }
    }
    // p*32 rows => +p*2048 bytes; swizzle phase unchanged ((32>>1)&3 == 0 mod 4)
    const uint32_t aDst = sbase + (tid >> 2) * 64 + ((((tid & 3)) ^ (((tid >> 2) >> 1) & 3)) << 4);
    // B: 4 k-groups of 8 per thread (kr = tid>>4 in 0..7); p*8 k-rows => +p*2048, k&7 phase unchanged
    const __half* bSrc = Wbase + (size_t)(tid >> 4) * N + (tid & 15) * 8;
    const uint32_t bDst = sbase + SM_BOFF + (tid >> 4) * 256 + (((tid & 15) ^ ((tid >> 4) & 7)) << 4);

    auto issue = [&](int kt2) {
        const uint32_t st = (uint32_t)(kt2 % NSTG) * STAGE;
#pragma unroll
        for (int h = 0; h < 2; h++) {
#pragma unroll
            for (int p = 0; p < 4; p++)
                cp16z(aDst + st + h * A_SUB + p * 2048,
                      aPtr[p] + kt2 * 64 + h * 32, aSz[p]);
            const __half* bp = bSrc + (size_t)(kt2 * 64 + h * 32) * N;
#pragma unroll
            for (int p = 0; p < 4; p++)
                cp16(bDst + st + h * B_SUB + p * 2048, bp + (size_t)p * 8 * N);
        }
    };

    uint32_t aA, bA;
    {
        int r0 = wm * 64 + (lane & 15);
        int c0 = lane >> 4;
        aA = sbase + r0 * 64 + ((c0 ^ ((r0 >> 1) & 3)) << 4);
        int k0 = lane & 15;
        int cb0 = wn * 8 + (lane >> 4);
        bA = sbase + SM_BOFF + k0 * 256 + ((cb0 ^ (k0 & 7)) << 4);
    }

    float c[4][8][4];
#pragma unroll
    for (int mf = 0; mf < 4; mf++)
#pragma unroll
        for (int nn = 0; nn < 8; nn++)
#pragma unroll
            for (int i = 0; i < 4; i++) c[mf][nn][i] = 0.f;

    issue(0); cp_commit();
    issue(1); cp_commit();

#pragma unroll 1
    for (int kt2 = 0; kt2 < KT2; kt2++) {
        cp_wait<1>();
        __syncthreads();
        if (kt2 + 2 < KT2) issue(kt2 + 2);
        cp_commit();

        const uint32_t st = (uint32_t)(kt2 % NSTG) * STAGE;
#pragma unroll
        for (int h = 0; h < 2; h++) {
            const uint32_t sA = aA + st + h * A_SUB;
            const uint32_t sB = bA + st + h * B_SUB;
#pragma unroll
            for (int kh = 0; kh < 2; kh++) {
                uint32_t a[4][4], b[4][4];
#pragma unroll
                for (int mf = 0; mf < 4; mf++)
                    ldsm4(a[mf], (sA + mf * 1024) ^ (kh << 5));
#pragma unroll
                for (int nf = 0; nf < 4; nf++)
                    ldsm4t(b[nf], (sB + kh * 4096) ^ (nf << 5));
#pragma unroll
                for (int mf = 0; mf < 4; mf++)
#pragma unroll
                    for (int nf = 0; nf < 4; nf++) {
                        mma16816(c[mf][nf * 2 + 0], a[mf], b[nf][0], b[nf][1]);
                        mma16816(c[mf][nf * 2 + 1], a[mf], b[nf][2], b[nf][3]);
                    }
            }
        }
    }
    __syncthreads();

    // ---- epilogue: fp16 output (g_h / g_yeh) via per-warp slab ----
    float* slab = reinterpret_cast<float*>(smem + wid * SLABB);
    const int er = lane >> 1, ec = (lane & 1) * 32;
#pragma unroll
    for (int mf = 0; mf < 4; mf++) {
#pragma unroll
        for (int nn = 0; nn < 8; nn++)
#pragma unroll
            for (int i = 0; i < 4; i++) {
                float v = c[mf][nn][i];
                if (FIRST) v = gelu_tanh(v);
                slab[(grp + (i >> 1) * 8) * SLABW + nn * 8 + qid * 2 + (i & 1)] = v;
            }
        __syncwarp();
        size_t row = (size_t)e * 1024 + by * BMT + wm * 64 + mf * 16 + er;
        int col = nb * BN + wn * 64 + ec;
        float v[32];
#pragma unroll
        for (int j = 0; j < 8; j++) {
            float4 t4 = *reinterpret_cast<const float4*>(slab + er * SLABW + ec + 4 * j);
            v[4 * j] = t4.x; v[4 * j + 1] = t4.y; v[4 * j + 2] = t4.z; v[4 * j + 3] = t4.w;
        }
        uint4* dst = reinterpret_cast<uint4*>((FIRST ? g_h : g_yeh) + row * N + col);
#pragma unroll
        for (int j = 0; j < 4; j++)
            dst[j] = make_uint4(pack2(v[8 * j], v[8 * j + 1]), pack2(v[8 * j + 2], v[8 * j + 3]),
                                pack2(v[8 * j + 4], v[8 * j + 5]), pack2(v[8 * j + 6], v[8 * j + 7]));
        __syncwarp();
    }
}

// ---------------- gather-free x convert (R14) ------------------------------------
// (x -> fp16 full tensor; gemm1 gathers rows directly via g_rows)

// ---------------- combine (fp16 y) -----------------------------------------------
__global__ void combine_kernel(const float* __restrict__ bias, float* __restrict__ out) {
    int t = blockIdx.x;
    int j = threadIdx.x;
    float4 acc = reinterpret_cast<const float4*>(bias)[j];
    int p0 = g_pos[t];
    int p1 = g_pos[TOKENS + t];
    float w0 = g_weight[t * 2 + 0], w1 = g_weight[t * 2 + 1];
    if (p0 >= 0) {
        uint2 hv = *reinterpret_cast<const uint2*>(g_yeh + (size_t)p0 * HS + 4 * j);
        float2 f0 = __half22float2(*reinterpret_cast<__half2*>(&hv.x));
        float2 f1 = __half22float2(*reinterpret_cast<__half2*>(&hv.y));
        acc.x += w0 * f0.x; acc.y += w0 * f0.y; acc.z += w0 * f1.x; acc.w += w0 * f1.y;
    }
    if (p1 >= 0) {
        uint2 hv = *reinterpret_cast<const uint2*>(g_yeh + (size_t)p1 * HS + 4 * j);
        float2 f0 = __half22float2(*reinterpret_cast<__half2*>(&hv.x));
        float2 f1 = __half22float2(*reinterpret_cast<__half2*>(&hv.y));
        acc.x += w1 * f0.x; acc.y += w1 * f0.y; acc.z += w1 * f1.x; acc.w += w1 * f1.y;
    }
    reinterpret_cast<float4*>(out + (size_t)t * HS)[j] = acc;
}

// ---------------- launch -----------------------------------------------------------
#define SMEMG (NSTG * (2 * 128 * 64 + 2 * 8192))   // 98304

extern "C" void kernel_launch(void* const* d_in, const int* in_sizes, int n_in,
                              void* d_out, int out_size) {
    const float* x    = (const float*)d_in[0];
    const float* rw   = (const float*)d_in[1];
    const float* w1   = (const float*)d_in[2];
    const float* w2   = (const float*)d_in[3];
    const float* bias = (const float*)d_in[4];
    float* out = (float*)d_out;

    static cudaStream_t s2 = nullptr, s3 = nullptr;
    static cudaEvent_t evA = nullptr, evG = nullptr, evX = nullptr, evW2 = nullptr;
    if (s2 == nullptr) {
        int loPri = 0, hiPri = 0;
        cudaDeviceGetStreamPriorityRange(&loPri, &hiPri);
        cudaStreamCreateWithFlags(&s2, cudaStreamNonBlocking);
        cudaStreamCreateWithPriority(&s3, cudaStreamNonBlocking, loPri);
        cudaEventCreateWithFlags(&evA, cudaEventDisableTiming);
        cudaEventCreateWithFlags(&evG, cudaEventDisableTiming);
        cudaEventCreateWithFlags(&evX, cudaEventDisableTiming);
        cudaEventCreateWithFlags(&evW2, cudaEventDisableTiming);
    }

    cudaFuncSetAttribute((const void*)moe_gemm<true>,
                         cudaFuncAttributeMaxDynamicSharedMemorySize, SMEMG);
    cudaFuncSetAttribute((const void*)moe_gemm<false>,
                         cudaFuncAttributeMaxDynamicSharedMemorySize, SMEMG);

    __half* w1h; cudaGetSymbolAddress((void**)&w1h, g_w1h);
    __half* w2h; cudaGetSymbolAddress((void**)&w2h, g_w2h);
    __half* xh;  cudaGetSymbolAddress((void**)&xh,  g_xh);
    __half* hh;  cudaGetSymbolAddress((void**)&hh,  g_h);

    const int WN4 = NE * HS * FFN / 4;
    const int XN4 = TOKENS * HS / 4;

    // R14 schedule: routing on s2; convert_x then convert_w2 on s3; convert_w1 on main
    cudaEventRecord(evA, 0);
    cudaStreamWaitEvent(s2, evA, 0);
    cudaStreamWaitEvent(s3, evA, 0);

    router_kernel<<<TOKENS / 8, 256, 0, s2>>>(x, rw);
    dispatch_kernel<<<1, 1024, 0, s2>>>();
    cudaEventRecord(evG, s2);                                   // g_rows ready

    convert_w<<<XN4 / 256, 256, 0, s3>>>(x, xh);                // x -> fp16
    cudaEventRecord(evX, s3);
    convert_w_strided<<<1184, 256, 0, s3>>>(w2, w2h, WN4);      // drains under gemm1
    cudaEventRecord(evW2, s3);                                  // w2h ready

    convert_w<<<WN4 / 256, 256>>>(w1, w1h);                     // main
    cudaStreamWaitEvent(0, evG, 0);
    cudaStreamWaitEvent(0, evX, 0);

    moe_gemm<true ><<<dim3(FFN / BN, 1024 / 128, NE), NTH, SMEMG>>>(xh, w1h);
    cudaStreamWaitEvent(0, evW2, 0);
    moe_gemm<false><<<dim3(HS / BN, 1024 / 128, NE), NTH, SMEMG>>>(hh, w2h);
    combine_kernel<<<TOKENS, 256>>>(bias, out);
}

// round 17
// speedup vs baseline: 1.0529x; 1.0041x over previous
#include <cuda_runtime.h>
#include <cuda_fp16.h>
#include <cstdint>
#include <math.h>

#define TOKENS 4096
#define HS 1024
#define FFN 4096
#define NE 8
#define CAP 512

// ---------------- scratch (static device globals; no allocations) -----------
__device__ int    g_expert[TOKENS * 2];
__device__ float  g_weight[TOKENS * 2];
__device__ int    g_rows[NE * 1024];
__device__ int    g_pos[2 * TOKENS];
__device__ __half g_xh[(size_t)TOKENS * HS];       // x fp16
__device__ __half g_w1h[(size_t)NE * HS * FFN];    // w1 fp16
__device__ __half g_w2h[(size_t)NE * FFN * HS];    // w2 fp16
__device__ __half g_h[(size_t)NE * 1024 * FFN];    // gemm1 out fp16
__device__ __half g_yeh[(size_t)NE * 1024 * HS];   // gemm2 out fp16

// ---------------- GEMM config -------------------------------------------------
#define BN 128
#define NTH 128                  // 4 warps, 64x64 per warp
#define NSTG 3
#define SLABW 68
#define SLABB (16 * SLABW * 4)

// ---------------- helpers -----------------------------------------------------
__device__ __forceinline__ uint32_t smem_u32(const void* p) {
    uint32_t a;
    asm("{ .reg .u64 t; cvta.to.shared.u64 t, %1; cvt.u32.u64 %0, t; }" : "=r"(a) : "l"(p));
    return a;
}
__device__ __forceinline__ uint32_t pack2(float lo, float hi) {
    __half2 h = __floats2half2_rn(lo, hi);
    return *reinterpret_cast<uint32_t*>(&h);
}
__device__ __forceinline__ void cp16(uint32_t sdst, const void* gsrc) {
    asm volatile("cp.async.cg.shared.global [%0], [%1], 16;" :: "r"(sdst), "l"(gsrc));
}
__device__ __forceinline__ void cp16z(uint32_t sdst, const void* gsrc, int nbytes) {
    asm volatile("cp.async.cg.shared.global [%0], [%1], 16, %2;"
                 :: "r"(sdst), "l"(gsrc), "r"(nbytes));
}
__device__ __forceinline__ void cp_commit() { asm volatile("cp.async.commit_group;"); }
template <int N> __device__ __forceinline__ void cp_wait() {
    asm volatile("cp.async.wait_group %0;" :: "n"(N));
}
__device__ __forceinline__ void ldsm4(uint32_t r[4], uint32_t addr) {
    asm volatile("ldmatrix.sync.aligned.m8n8.x4.shared.b16 {%0,%1,%2,%3}, [%4];"
                 : "=r"(r[0]), "=r"(r[1]), "=r"(r[2]), "=r"(r[3]) : "r"(addr));
}
__device__ __forceinline__ void ldsm4t(uint32_t r[4], uint32_t addr) {
    asm volatile("ldmatrix.sync.aligned.m8n8.x4.trans.shared.b16 {%0,%1,%2,%3}, [%4];"
                 : "=r"(r[0]), "=r"(r[1]), "=r"(r[2]), "=r"(r[3]) : "r"(addr));
}
__device__ __forceinline__ void mma16816(float c[4], const uint32_t a[4],
                                         uint32_t b0, uint32_t b1) {
    asm volatile(
        "mma.sync.aligned.m16n8k16.row.col.f32.f16.f16.f32 "
        "{%0,%1,%2,%3}, {%4,%5,%6,%7}, {%8,%9}, {%0,%1,%2,%3};"
        : "+f"(c[0]), "+f"(c[1]), "+f"(c[2]), "+f"(c[3])
        : "r"(a[0]), "r"(a[1]), "r"(a[2]), "r"(a[3]), "r"(b0), "r"(b1));
}
__device__ __forceinline__ float gelu_tanh(float v) {
    float v3 = v * v * v;
    return 0.5f * v * (1.0f + tanhf(0.7978845608028654f * (v + 0.044715f * v3)));
}

// ---------------- router -------------------------------------------------------
__global__ void router_kernel(const float* __restrict__ x, const float* __restrict__ rw) {
    int warp = threadIdx.x >> 5, lane = threadIdx.x & 31;
    int t = blockIdx.x * 8 + warp;
    const float* xr = x + (size_t)t * HS;
    float acc[NE];
#pragma unroll
    for (int e = 0; e < NE; e++) acc[e] = 0.f;
    for (int j = lane; j < HS; j += 32) {
        float xv = xr[j];
        const float4* r4 = reinterpret_cast<const float4*>(rw + (size_t)j * NE);
        float4 ra = r4[0], rb = r4[1];
        acc[0] += xv * ra.x; acc[1] += xv * ra.y; acc[2] += xv * ra.z; acc[3] += xv * ra.w;
        acc[4] += xv * rb.x; acc[5] += xv * rb.y; acc[6] += xv * rb.z; acc[7] += xv * rb.w;
    }
#pragma unroll
    for (int o = 16; o > 0; o >>= 1)
#pragma unroll
        for (int e = 0; e < NE; e++) acc[e] += __shfl_xor_sync(0xffffffffu, acc[e], o);
    if (lane == 0) {
        float m = acc[0];
#pragma unroll
        for (int e = 1; e < NE; e++) m = fmaxf(m, acc[e]);
        float s[NE]; float sum = 0.f;
#pragma unroll
        for (int e = 0; e < NE; e++) { s[e] = expf(acc[e] - m); sum += s[e]; }
        float inv = 1.f / sum;
        int e0 = 0; float m0 = s[0];
#pragma unroll
        for (int e = 1; e < NE; e++) if (s[e] > m0) { m0 = s[e]; e0 = e; }
        int e1 = -1; float m1 = -1.f;
#pragma unroll
        for (int e = 0; e < NE; e++) if (e != e0 && s[e] > m1) { m1 = s[e]; e1 = e; }
        g_expert[t * 2 + 0] = e0; g_expert[t * 2 + 1] = e1;
        g_weight[t * 2 + 0] = m0 * inv; g_weight[t * 2 + 1] = m1 * inv;
    }
}

// ---------------- dispatch: two-phase ------------------------------------------
__global__ void dispatch_kernel() {
    __shared__ int se[TOKENS * 2];
    __shared__ int chalf[16];
    for (int i = threadIdx.x; i < TOKENS * 2 / 4; i += 1024)
        reinterpret_cast<int4*>(se)[i] = reinterpret_cast<const int4*>(g_expert)[i];
    __syncthreads();

    int w = threadIdx.x >> 5, lane = threadIdx.x & 31;
    int pair = w >> 1, h = w & 1;
    int k = pair >> 3, e = pair & 7;

    if (h == 0) {
        int c = 0;
        for (int t = lane; t < TOKENS / 2; t += 32)
            c += (se[t * 2 + k] == e);
#pragma unroll
        for (int o = 16; o > 0; o >>= 1) c += __shfl_xor_sync(0xffffffffu, c, o);
        if (lane == 0) chalf[pair] = c;
    }
    __syncthreads();

    int count = h ? chalf[pair] : 0;
    const int base0 = h * (TOKENS / 2);
    for (int base = base0; base < base0 + TOKENS / 2; base += 32) {
        int t = base + lane;
        bool match = (se[t * 2 + k] == e);
        unsigned mask = __ballot_sync(0xffffffffu, match);
        int r = count + __popc(mask & ((1u << lane) - 1u));
        if (match) {
            if (r < CAP) {
                int slot = k * CAP + r;
                g_rows[e * 1024 + slot] = t;
                g_pos[k * TOKENS + t] = e * 1024 + slot;
            } else {
                g_pos[k * TOKENS + t] = -1;
            }
        }
        count += __popc(mask);
    }
    if (h == 1)
        for (int s = count + lane; s < CAP; s += 32)
            g_rows[e * 1024 + k * CAP + s] = -1;
}

// ---------------- f32 -> fp16 converts -------------------------------------------
__global__ void convert_w(const float* __restrict__ src, __half* __restrict__ dst) {
    int i = blockIdx.x * blockDim.x + threadIdx.x;
    float4 v = reinterpret_cast<const float4*>(src)[i];
    reinterpret_cast<uint2*>(dst)[i] = make_uint2(pack2(v.x, v.y), pack2(v.z, v.w));
}
__global__ void convert_w_strided(const float* __restrict__ src, __half* __restrict__ dst,
                                  int n4) {
    int stride = gridDim.x * blockDim.x;
    for (int i = blockIdx.x * blockDim.x + threadIdx.x; i < n4; i += stride) {
        float4 v = reinterpret_cast<const float4*>(src)[i];
        reinterpret_cast<uint2*>(dst)[i] = make_uint2(pack2(v.x, v.y), pack2(v.z, v.w));
    }
}

// ---------------- fp16 cp.async GEMM: 128 thr, 4 warps x (64x64), 2 CTAs/SM ------
template <bool FIRST>
__global__ void __launch_bounds__(NTH, 2)
moe_gemm(const __half* __restrict__ A0, const __half* __restrict__ W0) {
    constexpr int K = FIRST ? HS : FFN;
    constexpr int N = FIRST ? FFN : HS;
    constexpr int KT2 = K / 64;
    constexpr int BMT = 128;
    constexpr int A_SUB = BMT * 64;            // 8192
    constexpr int B_SUB = 8192;
    constexpr int STAGE = 2 * A_SUB + 2 * B_SUB;
    constexpr int SM_BOFF = 2 * A_SUB;
    extern __shared__ char smem[];
    const uint32_t sbase = smem_u32(smem);
    const int tid = threadIdx.x, wid = tid >> 5, lane = tid & 31;
    const int e = blockIdx.z, by = blockIdx.y, nb = blockIdx.x;
    const int wm = wid & 1, wn = wid >> 1;
    const int grp = lane >> 2, qid = lane & 3;

    const __half* Wbase = W0 + (size_t)e * K * N + nb * BN;

    const __half* aPtr[4];
    int aSz[4];
    {
        const int r = tid >> 2, kc = (tid & 3) * 8;
#pragma unroll
        for (int p = 0; p < 4; p++) {
            if (FIRST) {
                int tok = g_rows[e * 1024 + by * BMT + p * 32 + r];
                aSz[p] = (tok >= 0) ? 16 : 0;
                aPtr[p] = A0 + (size_t)(tok >= 0 ? tok : 0) * K + kc;
            } else {
                aSz[p] = 16;
                aPtr[p] = A0 + (size_t)(e * 1024 + by * BMT + p * 32 + r) * K + kc;
            }
        }
    }
    const uint32_t aDst = sbase + (tid >> 2) * 64 + ((((tid & 3)) ^ (((tid >> 2) >> 1) & 3)) << 4);
    const __half* bSrc = Wbase + (size_t)(tid >> 4) * N + (tid & 15) * 8;
    const uint32_t bDst = sbase + SM_BOFF + (tid >> 4) * 256 + (((tid & 15) ^ ((tid >> 4) & 7)) << 4);

    auto issue = [&](int kt2) {
        const uint32_t st = (uint32_t)(kt2 % NSTG) * STAGE;
#pragma unroll
        for (int h = 0; h < 2; h++) {
#pragma unroll
            for (int p = 0; p < 4; p++)
                cp16z(aDst + st + h * A_SUB + p * 2048,
                      aPtr[p] + kt2 * 64 + h * 32, aSz[p]);
            const __half* bp = bSrc + (size_t)(kt2 * 64 + h * 32) * N;
#pragma unroll
            for (int p = 0; p < 4; p++)
                cp16(bDst + st + h * B_SUB + p * 2048, bp + (size_t)p * 8 * N);
        }
    };

    uint32_t aA, bA;
    {
        int r0 = wm * 64 + (lane & 15);
        int c0 = lane >> 4;
        aA = sbase + r0 * 64 + ((c0 ^ ((r0 >> 1) & 3)) << 4);
        int k0 = lane & 15;
        int cb0 = wn * 8 + (lane >> 4);
        bA = sbase + SM_BOFF + k0 * 256 + ((cb0 ^ (k0 & 7)) << 4);
    }

    float c[4][8][4];
#pragma unroll
    for (int mf = 0; mf < 4; mf++)
#pragma unroll
        for (int nn = 0; nn < 8; nn++)
#pragma unroll
            for (int i = 0; i < 4; i++) c[mf][nn][i] = 0.f;

    issue(0); cp_commit();
    issue(1); cp_commit();

#pragma unroll 1
    for (int kt2 = 0; kt2 < KT2; kt2++) {
        cp_wait<1>();
        __syncthreads();
        if (kt2 + 2 < KT2) issue(kt2 + 2);
        cp_commit();

        const uint32_t st = (uint32_t)(kt2 % NSTG) * STAGE;
#pragma unroll
        for (int h = 0; h < 2; h++) {
            const uint32_t sA = aA + st + h * A_SUB;
            const uint32_t sB = bA + st + h * B_SUB;
#pragma unroll
            for (int kh = 0; kh < 2; kh++) {
                uint32_t a[4][4], b[4][4];
#pragma unroll
                for (int mf = 0; mf < 4; mf++)
                    ldsm4(a[mf], (sA + mf * 1024) ^ (kh << 5));
#pragma unroll
                for (int nf = 0; nf < 4; nf++)
                    ldsm4t(b[nf], (sB + kh * 4096) ^ (nf << 5));
#pragma unroll
                for (int mf = 0; mf < 4; mf++)
#pragma unroll
                    for (int nf = 0; nf < 4; nf++) {
                        mma16816(c[mf][nf * 2 + 0], a[mf], b[nf][0], b[nf][1]);
                        mma16816(c[mf][nf * 2 + 1], a[mf], b[nf][2], b[nf][3]);
                    }
            }
        }
    }
    __syncthreads();

    // ---- epilogue: fp16 output (g_h / g_yeh) via per-warp slab ----
    float* slab = reinterpret_cast<float*>(smem + wid * SLABB);
    const int er = lane >> 1, ec = (lane & 1) * 32;
#pragma unroll
    for (int mf = 0; mf < 4; mf++) {
#pragma unroll
        for (int nn = 0; nn < 8; nn++)
#pragma unroll
            for (int i = 0; i < 4; i++) {
                float v = c[mf][nn][i];
                if (FIRST) v = gelu_tanh(v);
                slab[(grp + (i >> 1) * 8) * SLABW + nn * 8 + qid * 2 + (i & 1)] = v;
            }
        __syncwarp();
        size_t row = (size_t)e * 1024 + by * BMT + wm * 64 + mf * 16 + er;
        int col = nb * BN + wn * 64 + ec;
        float v[32];
#pragma unroll
        for (int j = 0; j < 8; j++) {
            float4 t4 = *reinterpret_cast<const float4*>(slab + er * SLABW + ec + 4 * j);
            v[4 * j] = t4.x; v[4 * j + 1] = t4.y; v[4 * j + 2] = t4.z; v[4 * j + 3] = t4.w;
        }
        uint4* dst = reinterpret_cast<uint4*>((FIRST ? g_h : g_yeh) + row * N + col);
#pragma unroll
        for (int j = 0; j < 4; j++)
            dst[j] = make_uint4(pack2(v[8 * j], v[8 * j + 1]), pack2(v[8 * j + 2], v[8 * j + 3]),
                                pack2(v[8 * j + 4], v[8 * j + 5]), pack2(v[8 * j + 6], v[8 * j + 7]));
        __syncwarp();
    }
}

// ---------------- combine (fp16 y) -----------------------------------------------
__global__ void combine_kernel(const float* __restrict__ bias, float* __restrict__ out) {
    int t = blockIdx.x;
    int j = threadIdx.x;
    float4 acc = reinterpret_cast<const float4*>(bias)[j];
    int p0 = g_pos[t];
    int p1 = g_pos[TOKENS + t];
    float w0 = g_weight[t * 2 + 0], w1 = g_weight[t * 2 + 1];
    if (p0 >= 0) {
        uint2 hv = *reinterpret_cast<const uint2*>(g_yeh + (size_t)p0 * HS + 4 * j);
        float2 f0 = __half22float2(*reinterpret_cast<__half2*>(&hv.x));
        float2 f1 = __half22float2(*reinterpret_cast<__half2*>(&hv.y));
        acc.x += w0 * f0.x; acc.y += w0 * f0.y; acc.z += w0 * f1.x; acc.w += w0 * f1.y;
    }
    if (p1 >= 0) {
        uint2 hv = *reinterpret_cast<const uint2*>(g_yeh + (size_t)p1 * HS + 4 * j);
        float2 f0 = __half22float2(*reinterpret_cast<__half2*>(&hv.x));
        float2 f1 = __half22float2(*reinterpret_cast<__half2*>(&hv.y));
        acc.x += w1 * f0.x; acc.y += w1 * f0.y; acc.z += w1 * f1.x; acc.w += w1 * f1.y;
    }
    reinterpret_cast<float4*>(out + (size_t)t * HS)[j] = acc;
}

// ---------------- launch -----------------------------------------------------------
#define SMEMG (NSTG * (2 * 128 * 64 + 2 * 8192))   // 98304

extern "C" void kernel_launch(void* const* d_in, const int* in_sizes, int n_in,
                              void* d_out, int out_size) {
    const float* x    = (const float*)d_in[0];
    const float* rw   = (const float*)d_in[1];
    const float* w1   = (const float*)d_in[2];
    const float* w2   = (const float*)d_in[3];
    const float* bias = (const float*)d_in[4];
    float* out = (float*)d_out;

    static cudaStream_t s2 = nullptr, s3 = nullptr;
    static cudaEvent_t evA = nullptr, evG = nullptr, evX = nullptr;
    static cudaEvent_t evW1 = nullptr, evW2 = nullptr;
    if (s2 == nullptr) {
        int loPri = 0, hiPri = 0;
        cudaDeviceGetStreamPriorityRange(&loPri, &hiPri);
        cudaStreamCreateWithFlags(&s2, cudaStreamNonBlocking);
        cudaStreamCreateWithPriority(&s3, cudaStreamNonBlocking, loPri);
        cudaEventCreateWithFlags(&evA, cudaEventDisableTiming);
        cudaEventCreateWithFlags(&evG, cudaEventDisableTiming);
        cudaEventCreateWithFlags(&evX, cudaEventDisableTiming);
        cudaEventCreateWithFlags(&evW1, cudaEventDisableTiming);
        cudaEventCreateWithFlags(&evW2, cudaEventDisableTiming);
    }

    cudaFuncSetAttribute((const void*)moe_gemm<true>,
                         cudaFuncAttributeMaxDynamicSharedMemorySize, SMEMG);
    cudaFuncSetAttribute((const void*)moe_gemm<false>,
                         cudaFuncAttributeMaxDynamicSharedMemorySize, SMEMG);

    __half* w1h; cudaGetSymbolAddress((void**)&w1h, g_w1h);
    __half* w2h; cudaGetSymbolAddress((void**)&w2h, g_w2h);
    __half* xh;  cudaGetSymbolAddress((void**)&xh,  g_xh);
    __half* hh;  cudaGetSymbolAddress((void**)&hh,  g_h);

    const int WN4 = NE * HS * FFN / 4;
    const int XN4 = TOKENS * HS / 4;

    // fork: routing on s2; convert_x on s3 (then convert_w2 AFTER convert_w1
    // completes, so w1/w2 never contend for HBM); convert_w1 on main.
    cudaEventRecord(evA, 0);
    cudaStreamWaitEvent(s2, evA, 0);
    cudaStreamWaitEvent(s3, evA, 0);

    router_kernel<<<TOKENS / 8, 256, 0, s2>>>(x, rw);
    dispatch_kernel<<<1, 1024, 0, s2>>>();
    cudaEventRecord(evG, s2);                                   // g_rows ready

    convert_w<<<XN4 / 256, 256, 0, s3>>>(x, xh);                // x -> fp16 (light)
    cudaEventRecord(evX, s3);

    convert_w<<<WN4 / 256, 256>>>(w1, w1h);                     // main, full HBM
    cudaEventRecord(evW1, 0);                                   // w1h ready

    cudaStreamWaitEvent(s3, evW1, 0);
    convert_w_strided<<<1184, 256, 0, s3>>>(w2, w2h, WN4);      // drains under gemm1
    cudaEventRecord(evW2, s3);                                  // w2h ready

    cudaStreamWaitEvent(0, evG, 0);
    cudaStreamWaitEvent(0, evX, 0);

    moe_gemm<true ><<<dim3(FFN / BN, 1024 / 128, NE), NTH, SMEMG>>>(xh, w1h);
    cudaStreamWaitEvent(0, evW2, 0);
    moe_gemm<false><<<dim3(HS / BN, 1024 / 128, NE), NTH, SMEMG>>>(hh, w2h);
    combine_kernel<<<TOKENS, 256>>>(bias, out);
}